// round 15
// baseline (speedup 1.0000x reference)
#include <cuda_runtime.h>
#include <cuda_bf16.h>
#include <math.h>
#include <stdint.h>

// Problem constants
#define BATCH   2
#define SEQ     1024
#define DMODEL  1024
#define NHEADS  16
#define DHEAD   64
#define NTOK    (BATCH*SEQ)          // 2048
#define NBHT    (BATCH*NHEADS*SEQ)   // 32768
#define FDIM    48                   // compressed feature dim (45 used, padded 48)
#define EPS_PSD 0.001f

// -------- device scratch (static, no allocations) --------
__device__ float g_q[NBHT*DHEAD];
__device__ float g_k[NBHT*DHEAD];
__device__ float g_cos[SEQ*32];
__device__ float g_sin[SEQ*32];
__device__ float g_po[2*NTOK*DMODEL];            // final gemm K-split partials

__device__ __nv_bfloat16 g_xh[NTOK*DMODEL];
__device__ __nv_bfloat16 g_xl[NTOK*DMODEL];
__device__ __nv_bfloat16 g_wth[4*DMODEL*DMODEL]; // Wq,Wk,Wv,Wo transposed [n][k]
__device__ __nv_bfloat16 g_wtl[4*DMODEL*DMODEL];

__device__ __nv_bfloat16 g_vh[NBHT*DHEAD];       // V bf16 hi/lo [bh][t][d]
__device__ __nv_bfloat16 g_vl[NBHT*DHEAD];

__device__ __nv_bfloat16 g_uh[NBHT*FDIM];        // u rows bf16 hi [n][48]
__device__ __nv_bfloat16 g_wh[NBHT*FDIM];        // w rows bf16 hi/lo [n][48]
__device__ __nv_bfloat16 g_wl[NBHT*FDIM];

__device__ __nv_bfloat16 g_a2h[NTOK*DMODEL];     // attention out, token-major
__device__ __nv_bfloat16 g_a2l[NTOK*DMODEL];

// ============================================================
// PTX helpers
// ============================================================
__device__ __forceinline__ uint32_t smem_u32(const void* p) {
    uint32_t a;
    asm("{ .reg .u64 t; cvta.to.shared.u64 t, %1; cvt.u32.u64 %0, t; }" : "=r"(a) : "l"(p));
    return a;
}
__device__ __forceinline__ void ldmatrix_x4(uint32_t* r, uint32_t addr) {
    asm volatile("ldmatrix.sync.aligned.m8n8.x4.shared.b16 {%0,%1,%2,%3}, [%4];"
        : "=r"(r[0]), "=r"(r[1]), "=r"(r[2]), "=r"(r[3]) : "r"(addr));
}
__device__ __forceinline__ void ldmatrix_x2(uint32_t* r, uint32_t addr) {
    asm volatile("ldmatrix.sync.aligned.m8n8.x2.shared.b16 {%0,%1}, [%2];"
        : "=r"(r[0]), "=r"(r[1]) : "r"(addr));
}
__device__ __forceinline__ void ldmatrix_x2_trans(uint32_t* r, uint32_t addr) {
    asm volatile("ldmatrix.sync.aligned.m8n8.x2.trans.shared.b16 {%0,%1}, [%2];"
        : "=r"(r[0]), "=r"(r[1]) : "r"(addr));
}
__device__ __forceinline__ void mma16816(float* c, const uint32_t* a, const uint32_t* b) {
    asm volatile("mma.sync.aligned.m16n8k16.row.col.f32.bf16.bf16.f32 "
        "{%0,%1,%2,%3}, {%4,%5,%6,%7}, {%8,%9}, {%0,%1,%2,%3};"
        : "+f"(c[0]), "+f"(c[1]), "+f"(c[2]), "+f"(c[3])
        : "r"(a[0]), "r"(a[1]), "r"(a[2]), "r"(a[3]), "r"(b[0]), "r"(b[1]));
}
#define CP_ASYNC16(saddr, gptr) \
    asm volatile("cp.async.cg.shared.global [%0], [%1], 16;" \
        :: "r"(saddr), "l"(gptr) : "memory")
#define CP_COMMIT() asm volatile("cp.async.commit_group;" ::: "memory")
#define CP_WAIT(N)  asm volatile("cp.async.wait_group %0;" :: "n"(N) : "memory")

__device__ __forceinline__ void split2(float v0, float v1, uint32_t& h, uint32_t& l) {
    __nv_bfloat16 h0 = __float2bfloat16(v0), h1 = __float2bfloat16(v1);
    __nv_bfloat162 hp; hp.x = h0; hp.y = h1;
    h = *(uint32_t*)&hp;
    __nv_bfloat16 l0 = __float2bfloat16(v0 - __bfloat162float(h0));
    __nv_bfloat16 l1 = __float2bfloat16(v1 - __bfloat162float(h1));
    __nv_bfloat162 lp; lp.x = l0; lp.y = l1;
    l = *(uint32_t*)&lp;
}

// ============================================================
// Conversion + table kernels
// ============================================================
__global__ void xconv_kernel(const float* __restrict__ x,
                             __nv_bfloat16* __restrict__ xh,
                             __nv_bfloat16* __restrict__ xl)
{
    int i = blockIdx.x * blockDim.x + threadIdx.x;
    if (i >= NTOK*DMODEL) return;
    float v = x[i];
    __nv_bfloat16 h = __float2bfloat16(v);
    xh[i] = h;
    xl[i] = __float2bfloat16(v - __bfloat162float(h));
}

__global__ void wconv_kernel(const float* __restrict__ W0, const float* __restrict__ W1,
                             const float* __restrict__ W2, const float* __restrict__ W3,
                             __nv_bfloat16* __restrict__ th, __nv_bfloat16* __restrict__ tl)
{
    __shared__ float s[32][33];
    const float* W = (blockIdx.z == 0) ? W0 : (blockIdx.z == 1) ? W1
                   : (blockIdx.z == 2) ? W2 : W3;
    size_t zoff = (size_t)blockIdx.z * DMODEL * DMODEL;
    bool need_lo = (blockIdx.z >= 2);   // Wq/Wk used at bf16x1 (hi only)
    int n0 = blockIdx.x * 32, k0 = blockIdx.y * 32;
    int tx = threadIdx.x, ty = threadIdx.y;   // 32 x 8
    #pragma unroll
    for (int j = 0; j < 4; j++)
        s[ty + j*8][tx] = W[(size_t)(k0 + ty + j*8)*DMODEL + n0 + tx];
    __syncthreads();
    #pragma unroll
    for (int j = 0; j < 4; j++) {
        float v = s[tx][ty + j*8];
        __nv_bfloat16 h = __float2bfloat16(v);
        size_t o = zoff + (size_t)(n0 + ty + j*8)*DMODEL + k0 + tx;
        th[o] = h;
        if (need_lo) tl[o] = __float2bfloat16(v - __bfloat162float(h));
    }
}

__global__ void rope_table_kernel(float* __restrict__ ct, float* __restrict__ st)
{
    int idx = blockIdx.x * blockDim.x + threadIdx.x;
    if (idx >= SEQ*32) return;
    int i = idx & 31, t = idx >> 5;
    float inv = (float)(1.0 / pow(10000.0, (double)i / 32.0));
    float ang = (float)t * inv;
    float s, c;
    sincosf(ang, &s, &c);
    ct[idx] = c;
    st[idx] = s;
}

// sum the two final-gemm K-split partials into d_out
__global__ void sum_kernel(const float* __restrict__ po, float* __restrict__ out)
{
    int i = blockIdx.x * blockDim.x + threadIdx.x;
    if (i >= NTOK*DMODEL) return;
    out[i] = po[i] + po[NTOK*DMODEL + i];
}

// ============================================================
// mma.sync bf16 split GEMM, 128x128 CTA tile, 8 warps (2m x 4n),
// warp = 64x32 via 4x4 m16n8k16; mt-half inner loop; 2-stage
// cp.async, single sync per chunk; 2 CTAs/SM.
// MODE 0: half-K (z = k-half), f32 partial out [z][M][N], bf16x3.
// MODE 1: full-K fused QKV, role interleaved at stride 3 in the
//   linear block id (v,q,k,v,q,k,...) so heavy x3 V CTAs mix with
//   light x1 q/k CTAs on each SM.
//   role 0 -> v (bf16x3, bf16 hi/lo scatter); 1 -> q, 2 -> k (bf16x1).
// ============================================================
#define KC 32
#define ROW_STRIDE 40
#define MAT_BYTES (128*ROW_STRIDE*2)       // 10240
#define STAGE_BYTES (4*MAT_BYTES)          // 40960 (Ah, Al, Bh, Bl)
#define GEMM_SMEM (2*STAGE_BYTES)          // 81920

template<int MODE>
__global__ __launch_bounds__(256, 2)
void mma_gemm(const __nv_bfloat16* __restrict__ Ah, const __nv_bfloat16* __restrict__ Al,
              const __nv_bfloat16* __restrict__ Bh0, const __nv_bfloat16* __restrict__ Bl0,
              float* __restrict__ C0, float* __restrict__ C1,
              __nv_bfloat16* __restrict__ Cvh, __nv_bfloat16* __restrict__ Cvl)
{
    extern __shared__ char smem[];
    uint32_t sbase = smem_u32(smem);
    int tid = threadIdx.x, wid = tid >> 5, lane = tid & 31;

    int n0, m0, z;
    if (MODE == 1) {
        int lid  = (int)(blockIdx.x + 8*blockIdx.y + 128*blockIdx.z);  // 0..383
        int role = lid % 3;              // 0=v, 1=q, 2=k (interleaved)
        int tile = lid / 3;              // 0..127
        n0 = (tile & 7) * 128;
        m0 = (tile >> 3) * 128;
        z  = (role == 0) ? 2 : role - 1; // logical z: 0=q, 1=k, 2=v
    } else {
        n0 = blockIdx.x * 128;
        m0 = blockIdx.y * 128;
        z  = blockIdx.z;
    }
    const int KTOT = (MODE == 0) ? 512 : 1024;
    int koff = (MODE == 0) ? z * 512 : 0;
    const bool x3 = (MODE == 0) || (z == 2);   // uniform per CTA; else bf16x1

    const __nv_bfloat16* Bh = Bh0 + ((MODE == 1) ? (size_t)z * DMODEL * DMODEL : 0);
    const __nv_bfloat16* Bl = Bl0 + ((MODE == 1) ? (size_t)z * DMODEL * DMODEL : 0);

    int mat = tid >> 6;        // 0=Ah 1=Al 2=Bh 3=Bl
    int tp  = tid & 63;
    // x1 mode: Al/Bl unused; mats 0,1 split Ah rows; mats 2,3 split Bh rows.
    int srcmat = mat;
    int itlo = 0, ithi = 8;
    if (!x3) {
        if (mat == 0)      { ithi = 4; }
        else if (mat == 1) { srcmat = 0; itlo = 4; }
        else if (mat == 2) { ithi = 4; }
        else               { srcmat = 2; itlo = 4; }
    }
    const __nv_bfloat16* gsrc =
        (srcmat == 0) ? Ah + (size_t)m0*DMODEL + koff :
        (srcmat == 1) ? Al + (size_t)m0*DMODEL + koff :
        (srcmat == 2) ? Bh + (size_t)n0*DMODEL + koff :
                        Bl + (size_t)n0*DMODEL + koff;
    uint32_t moff = (uint32_t)srcmat * MAT_BYTES;

    int warp_m = wid & 1, warp_n = wid >> 1;

    float acc[4][4][4];
    #pragma unroll
    for (int a = 0; a < 4; a++)
        #pragma unroll
        for (int b = 0; b < 4; b++)
            #pragma unroll
            for (int c = 0; c < 4; c++) acc[a][b][c] = 0.f;

    #define GEMM_ISSUE(chunk, slot) do { \
        const __nv_bfloat16* g = gsrc + (chunk)*KC; \
        uint32_t sdst = sbase + (slot)*STAGE_BYTES + moff; \
        for (int it = itlo; it < ithi; it++) { \
            int idx = tp + it*64; \
            int row = idx >> 2, c4 = idx & 3; \
            CP_ASYNC16(sdst + row*(ROW_STRIDE*2) + c4*16, \
                       g + (size_t)row*DMODEL + c4*8); \
        } \
        CP_COMMIT(); \
    } while (0)

    GEMM_ISSUE(0, 0);

    for (int c = 0; c < KTOT/KC; c++) {
        int slot = c & 1;
        CP_WAIT(0);
        __syncthreads();
        if (c + 1 < KTOT/KC) GEMM_ISSUE(c + 1, slot ^ 1);

        uint32_t b_off = sbase + slot*STAGE_BYTES;
        #pragma unroll
        for (int ks = 0; ks < 2; ks++) {
            int k0 = ks * 16;
            uint32_t b_h[4][2], b_l[4][2];
            #pragma unroll
            for (int ntp = 0; ntp < 2; ntp++) {
                int row = warp_n*32 + ntp*16 + (lane & 7) + ((lane >> 4) << 3);
                uint32_t col = k0 + (((lane >> 3) & 1) << 3);
                uint32_t off = b_off + 2*MAT_BYTES + (row*ROW_STRIDE + col)*2;
                uint32_t rh[4], rl[4];
                ldmatrix_x4(rh, off);
                b_h[ntp*2+0][0] = rh[0]; b_h[ntp*2+0][1] = rh[1];
                b_h[ntp*2+1][0] = rh[2]; b_h[ntp*2+1][1] = rh[3];
                if (x3) {
                    ldmatrix_x4(rl, off + MAT_BYTES);
                    b_l[ntp*2+0][0] = rl[0]; b_l[ntp*2+0][1] = rl[1];
                    b_l[ntp*2+1][0] = rl[2]; b_l[ntp*2+1][1] = rl[3];
                }
            }
            #pragma unroll
            for (int half = 0; half < 2; half++) {
                uint32_t a_h[2][4], a_l[2][4];
                #pragma unroll
                for (int m2 = 0; m2 < 2; m2++) {
                    int mt = half*2 + m2;
                    int row = warp_m*64 + mt*16 + (lane & 15);
                    uint32_t col = k0 + ((lane >> 4) << 3);
                    uint32_t off = b_off + (row*ROW_STRIDE + col)*2;
                    ldmatrix_x4(a_h[m2], off);
                    if (x3) ldmatrix_x4(a_l[m2], off + MAT_BYTES);
                }
                #pragma unroll
                for (int m2 = 0; m2 < 2; m2++)
                    #pragma unroll
                    for (int nt = 0; nt < 4; nt++)
                        mma16816(acc[half*2+m2][nt], a_h[m2], b_h[nt]);
                if (x3) {
                    #pragma unroll
                    for (int m2 = 0; m2 < 2; m2++)
                        #pragma unroll
                        for (int nt = 0; nt < 4; nt++)
                            mma16816(acc[half*2+m2][nt], a_h[m2], b_l[nt]);
                    #pragma unroll
                    for (int m2 = 0; m2 < 2; m2++)
                        #pragma unroll
                        for (int nt = 0; nt < 4; nt++)
                            mma16816(acc[half*2+m2][nt], a_l[m2], b_h[nt]);
                }
            }
        }
    }

    // epilogue
    int qrow = lane >> 2, qcol = (lane & 3) * 2;
    float* Cp = (MODE == 0) ? (C0 + (size_t)z * NTOK * DMODEL) : nullptr;
    #pragma unroll
    for (int mt = 0; mt < 4; mt++) {
        #pragma unroll
        for (int nt = 0; nt < 4; nt++) {
            int row0 = m0 + warp_m*64 + mt*16 + qrow;
            int col  = n0 + warp_n*32 + nt*8 + qcol;
            float2 v0 = make_float2(acc[mt][nt][0], acc[mt][nt][1]);
            float2 v1 = make_float2(acc[mt][nt][2], acc[mt][nt][3]);
            if (MODE == 0) {
                *(float2*)&Cp[(size_t)row0*DMODEL + col] = v0;
                *(float2*)&Cp[(size_t)(row0 + 8)*DMODEL + col] = v1;
            } else if (z < 2) {
                float* C = z ? C1 : C0;
                int h = col >> 6, d = col & 63;
                int b0 = row0 >> 10, t0 = row0 & 1023;
                *(float2*)&C[((size_t)((b0*NHEADS + h)*SEQ + t0))*DHEAD + d] = v0;
                int r1 = row0 + 8;
                int b1 = r1 >> 10, t1 = r1 & 1023;
                *(float2*)&C[((size_t)((b1*NHEADS + h)*SEQ + t1))*DHEAD + d] = v1;
            } else {
                int h = col >> 6, d = col & 63;
                #pragma unroll
                for (int rr = 0; rr < 2; rr++) {
                    int row = row0 + rr*8;
                    float2 v = rr ? v1 : v0;
                    int b = row >> 10, t = row & 1023;
                    size_t o = ((size_t)((b*NHEADS + h)*SEQ + t))*DHEAD + d;
                    __nv_bfloat16 h0 = __float2bfloat16(v.x), h1 = __float2bfloat16(v.y);
                    __nv_bfloat162 hp; hp.x = h0; hp.y = h1;
                    *(__nv_bfloat162*)&Cvh[o] = hp;
                    __nv_bfloat162 lp;
                    lp.x = __float2bfloat16(v.x - __bfloat162float(h0));
                    lp.y = __float2bfloat16(v.y - __bfloat162float(h1));
                    *(__nv_bfloat162*)&Cvl[o] = lp;
                }
            }
        }
    }
}

// ============================================================
// Feature kernel, fused RoPE -> compressed 48-dim features.
// u rows: bf16 hi only. w rows: bf16 hi/lo.
// Feature layout (45 used):
//   [0..7]   u=2*Gq[d],        w=km[d]
//   [8..15]  u=-G[d][d],       w=km[d]^2
//   [16..43] u=-2*G[d][f] d<f, w=km[d]*km[f]
//   [44]     u=-qGq,           w=1
//   [45..47] zero padding
// ============================================================
__global__ void feature_kernel(const float* __restrict__ q, const float* __restrict__ k,
                               const float* __restrict__ ct, const float* __restrict__ st,
                               const float* __restrict__ Wqm, const float* __restrict__ Wkm,
                               const float* __restrict__ Wm,
                               __nv_bfloat16* __restrict__ uhg,
                               __nv_bfloat16* __restrict__ whg, __nv_bfloat16* __restrict__ wlg)
{
    __shared__ float sWqm[512], sWkm[512], sWm[512];
    __shared__ float sOut[64][51];

    int tid = threadIdx.x;           // 64 threads
    int n0 = blockIdx.x * 64;
    int n  = n0 + tid;
    int t  = n & 1023;

    for (int p = tid; p < 512; p += 64) {
        sWqm[p] = Wqm[p]; sWkm[p] = Wkm[p]; sWm[p] = Wm[p];
    }
    __syncthreads();

    const float4* qr = (const float4*)(q + (size_t)n*64);
    const float4* kr = (const float4*)(k + (size_t)n*64);
    const float4* cp4 = (const float4*)(ct + (size_t)t*32);
    const float4* sp4 = (const float4*)(st + (size_t)t*32);

    float qm[8], km[8];
    #pragma unroll
    for (int m = 0; m < 8; m++) { qm[m] = 0.f; km[m] = 0.f; }
    #pragma unroll
    for (int d4 = 0; d4 < 8; d4++) {
        float4 q1 = qr[d4], q2 = qr[d4+8];
        float4 k1 = kr[d4], k2 = kr[d4+8];
        float4 cv = cp4[d4], sv = sp4[d4];
        const float* q1f = (const float*)&q1;
        const float* q2f = (const float*)&q2;
        const float* k1f = (const float*)&k1;
        const float* k2f = (const float*)&k2;
        const float* cf  = (const float*)&cv;
        const float* sf  = (const float*)&sv;
        #pragma unroll
        for (int j = 0; j < 4; j++) {
            int i = d4*4 + j;
            float c = cf[j], s = sf[j];
            float qa = q1f[j]*c - q2f[j]*s;
            float qb = q1f[j]*s + q2f[j]*c;
            float ka = k1f[j]*c - k2f[j]*s;
            float kb = k1f[j]*s + k2f[j]*c;
            #pragma unroll
            for (int m = 0; m < 8; m++) {
                qm[m] = fmaf(qa, sWqm[i*8+m], fmaf(qb, sWqm[(i+32)*8+m], qm[m]));
                km[m] = fmaf(ka, sWkm[i*8+m], fmaf(kb, sWkm[(i+32)*8+m], km[m]));
            }
        }
    }
    #pragma unroll
    for (int m = 0; m < 8; m++) {
        qm[m] = 1.0f / (1.0f + expf(-qm[m]));
        km[m] = 1.0f / (1.0f + expf(-km[m]));
    }

    float A[64];
    #pragma unroll
    for (int nn = 0; nn < 64; nn++) {
        float s = 0.f;
        #pragma unroll
        for (int m = 0; m < 8; m++) s = fmaf(qm[m], sWm[m*64+nn], s);
        A[nn] = s;
    }

    // G symmetric: compute diag + upper triangle only
    float Gq[8];
    #pragma unroll
    for (int d = 0; d < 8; d++) Gq[d] = 0.f;
    {
        int pc = 16;
        #pragma unroll
        for (int d = 0; d < 8; d++) {
            #pragma unroll
            for (int f = d; f < 8; f++) {
                float g = 0.f;
                #pragma unroll
                for (int e = 0; e < 8; e++) g = fmaf(A[d*8+e], A[f*8+e], g);
                if (f == d) {
                    g += EPS_PSD;
                    sOut[tid][8 + d] = -g;
                    Gq[d] = fmaf(g, qm[d], Gq[d]);
                } else {
                    sOut[tid][pc++] = -2.0f * g;
                    Gq[d] = fmaf(g, qm[f], Gq[d]);
                    Gq[f] = fmaf(g, qm[d], Gq[f]);
                }
            }
        }
    }
    float qGq = 0.f;
    #pragma unroll
    for (int d = 0; d < 8; d++) {
        qGq = fmaf(Gq[d], qm[d], qGq);
        sOut[tid][d] = 2.0f * Gq[d];
    }
    sOut[tid][44] = -qGq;
    sOut[tid][45] = 0.f; sOut[tid][46] = 0.f; sOut[tid][47] = 0.f;
    __syncthreads();

    // u: hi only
    for (int p = tid; p < 64*FDIM; p += 64) {
        int r = p / FDIM, c = p % FDIM;
        uhg[(size_t)(n0 + r)*FDIM + c] = __float2bfloat16(sOut[r][c]);
    }
    __syncthreads();

    // w features
    {
        #pragma unroll
        for (int d = 0; d < 8; d++) sOut[tid][d] = km[d];
        #pragma unroll
        for (int d = 0; d < 8; d++) sOut[tid][8 + d] = km[d]*km[d];
        int pc = 16;
        #pragma unroll
        for (int d = 0; d < 8; d++)
            #pragma unroll
            for (int f = d+1; f < 8; f++)
                sOut[tid][pc++] = km[d]*km[f];
        sOut[tid][44] = 1.0f;
        sOut[tid][45] = 0.f; sOut[tid][46] = 0.f; sOut[tid][47] = 0.f;
    }
    __syncthreads();

    for (int p = tid; p < 64*FDIM; p += 64) {
        int r = p / FDIM, c = p % FDIM;
        float v = sOut[r][c];
        __nv_bfloat16 h = __float2bfloat16(v);
        size_t o = (size_t)(n0 + r)*FDIM + c;
        whg[o] = h;
        wlg[o] = __float2bfloat16(v - __bfloat162float(h));
    }
}

// ============================================================
// Tensor-core flash on 48-dim features:
// S = U.W^T with U hi-only (bf16x2: uh*wh + uh*wl), 3 k-steps;
// P = exp(min(S,0)/temp) (S<=0, no max tracking); O = P.V (bf16x3);
// split-k over warp_n. 64x64 tiles, 8 warps; 2-stage cp.async; 2 CTAs/SM.
// ============================================================
#define FL_USTR 56
#define FL_VSTR 72
#define FL_UMAT (64*FL_USTR*2)              // 7168
#define FL_OFF_W  FL_UMAT                   // 7168
#define FL_WBUF   (2*FL_UMAT)               // 14336 (h + l)
#define FL_OFF_V  (FL_OFF_W + 2*FL_WBUF)    // 35840
#define FL_VBUF   (2*64*FL_VSTR*2)          // 18432
#define FLASH_SMEM (FL_OFF_V + 2*FL_VBUF)   // 72704

__global__ __launch_bounds__(256, 2)
void flash_mma(const __nv_bfloat16* __restrict__ uh,
               const __nv_bfloat16* __restrict__ wh, const __nv_bfloat16* __restrict__ wl,
               const __nv_bfloat16* __restrict__ vh, const __nv_bfloat16* __restrict__ vl,
               __nv_bfloat16* __restrict__ oh, __nv_bfloat16* __restrict__ ol,
               const float* __restrict__ temperature)
{
    extern __shared__ char smem[];
    uint32_t sb = smem_u32(smem);
    int tid = threadIdx.x, wid = tid >> 5, lane = tid & 31;
    int warp_m = wid & 1, warp_n = wid >> 1;
    int bh = blockIdx.y;
    int ib = (int)(gridDim.x - 1 - blockIdx.x);
    float inv_temp = 1.f / fmaxf(temperature[0], 0.1f);

    // U tile load (hi only: 64 rows x 96B, stride 112B)
    {
        const char* gh = (const char*)(uh + (size_t)(bh*SEQ + ib*64)*FDIM);
        for (int p = tid; p < 384; p += 256) {
            int r = p / 6, c = p % 6;
            CP_ASYNC16(sb + r*(FL_USTR*2) + c*16, gh + r*96 + c*16);
        }
    }
    #define ISSUE_WV(jb, buf) do { \
        const char* gwh = (const char*)(wh + (size_t)(bh*SEQ + (jb)*64)*FDIM); \
        const char* gwl = (const char*)(wl + (size_t)(bh*SEQ + (jb)*64)*FDIM); \
        uint32_t wdst = sb + FL_OFF_W + (buf)*FL_WBUF; \
        for (int p = tid; p < 384; p += 256) { \
            int r = p / 6, c = p % 6; \
            CP_ASYNC16(wdst + r*(FL_USTR*2) + c*16, gwh + r*96 + c*16); \
            CP_ASYNC16(wdst + FL_UMAT + r*(FL_USTR*2) + c*16, gwl + r*96 + c*16); \
        } \
        const char* gvh = (const char*)(vh + (size_t)(bh*SEQ + (jb)*64)*DHEAD); \
        const char* gvl = (const char*)(vl + (size_t)(bh*SEQ + (jb)*64)*DHEAD); \
        uint32_t vdst = sb + FL_OFF_V + (buf)*FL_VBUF; \
        for (int p = tid; p < 512; p += 256) { \
            int r = p / 8, c = p % 8; \
            CP_ASYNC16(vdst + r*144 + c*16, gvh + r*128 + c*16); \
            CP_ASYNC16(vdst + 9216 + r*144 + c*16, gvl + r*128 + c*16); \
        } \
    } while (0)

    ISSUE_WV(0, 0);
    CP_COMMIT();

    float accO[2][8][4];
    float l_acc[4];
    #pragma unroll
    for (int i = 0; i < 4; i++) l_acc[i] = 0.f;
    #pragma unroll
    for (int mt = 0; mt < 2; mt++)
        #pragma unroll
        for (int nt = 0; nt < 8; nt++)
            #pragma unroll
            for (int r = 0; r < 4; r++) accO[mt][nt][r] = 0.f;

    for (int jb = 0; jb <= ib; jb++) {
        int buf = jb & 1;
        CP_WAIT(0);
        __syncthreads();
        if (jb < ib) { ISSUE_WV(jb+1, buf^1); CP_COMMIT(); }

        uint32_t sw_h = sb + FL_OFF_W + buf*FL_WBUF;
        uint32_t sw_l = sw_h + FL_UMAT;
        uint32_t sv_h = sb + FL_OFF_V + buf*FL_VBUF;
        uint32_t sv_l = sv_h + 9216;

        // ---- S = U . W^T  (bf16x2, 3 k-steps over 48 features) ----
        float sc[2][2][4];
        #pragma unroll
        for (int mt = 0; mt < 2; mt++)
            #pragma unroll
            for (int nt = 0; nt < 2; nt++)
                #pragma unroll
                for (int r = 0; r < 4; r++) sc[mt][nt][r] = 0.f;

        #pragma unroll
        for (int k5 = 0; k5 < 3; k5++) {
            int k0 = k5*16;
            uint32_t a_h[2][4], b_h[2][2], b_l[2][2];
            #pragma unroll
            for (int mt = 0; mt < 2; mt++) {
                int row = warp_m*32 + mt*16 + (lane & 15);
                uint32_t off = (uint32_t)(row*FL_USTR + k0 + ((lane >> 4) << 3))*2;
                ldmatrix_x4(a_h[mt], sb + off);
            }
            #pragma unroll
            for (int nt = 0; nt < 2; nt++) {
                int row = warp_n*16 + nt*8 + (lane & 7);
                uint32_t off = (uint32_t)(row*FL_USTR + k0 + (((lane >> 3) & 1) << 3))*2;
                ldmatrix_x2(b_h[nt], sw_h + off);
                ldmatrix_x2(b_l[nt], sw_l + off);
            }
            #pragma unroll
            for (int mt = 0; mt < 2; mt++)
                #pragma unroll
                for (int nt = 0; nt < 2; nt++)
                    mma16816(sc[mt][nt], a_h[mt], b_h[nt]);
            #pragma unroll
            for (int mt = 0; mt < 2; mt++)
                #pragma unroll
                for (int nt = 0; nt < 2; nt++)
                    mma16816(sc[mt][nt], a_h[mt], b_l[nt]);
        }

        // ---- P = exp(min(S,0)/temp), causal mask, row-sum partials ----
        bool diag = (jb == ib);
        uint32_t ph[2][4], pl[2][4];
        #pragma unroll
        for (int mt = 0; mt < 2; mt++) {
            #pragma unroll
            for (int half = 0; half < 2; half++) {
                int t_g = ib*64 + warp_m*32 + mt*16 + (lane >> 2) + half*8;
                float pv[4];
                #pragma unroll
                for (int nt = 0; nt < 2; nt++) {
                    #pragma unroll
                    for (int cc = 0; cc < 2; cc++) {
                        int s_g = jb*64 + warp_n*16 + nt*8 + (lane & 3)*2 + cc;
                        float v = sc[mt][nt][half*2 + cc];
                        float p = __expf(fminf(v, 0.f) * inv_temp);
                        if (diag && s_g > t_g) p = 0.f;
                        pv[nt*2 + cc] = p;
                    }
                }
                float ls = pv[0] + pv[1] + pv[2] + pv[3];
                ls += __shfl_xor_sync(0xffffffffu, ls, 1);
                ls += __shfl_xor_sync(0xffffffffu, ls, 2);
                l_acc[mt*2 + half] += ls;
                split2(pv[0], pv[1], ph[mt][half], pl[mt][half]);
                split2(pv[2], pv[3], ph[mt][2 + half], pl[mt][2 + half]);
            }
        }

        // ---- O += P . V  (k-slice = warp_n's 16 s) ----
        #pragma unroll
        for (int ntp = 0; ntp < 4; ntp++) {
            uint32_t v_h[2][2], v_l[2][2];
            #pragma unroll
            for (int q2 = 0; q2 < 2; q2++) {
                int nt = ntp*2 + q2;
                uint32_t off = (uint32_t)((warp_n*16 + (lane & 15))*FL_VSTR + nt*8)*2;
                ldmatrix_x2_trans(v_h[q2], sv_h + off);
                ldmatrix_x2_trans(v_l[q2], sv_l + off);
            }
            #pragma unroll
            for (int mt = 0; mt < 2; mt++)
                #pragma unroll
                for (int q2 = 0; q2 < 2; q2++)
                    mma16816(accO[mt][ntp*2+q2], ph[mt], v_h[q2]);
            #pragma unroll
            for (int mt = 0; mt < 2; mt++)
                #pragma unroll
                for (int q2 = 0; q2 < 2; q2++)
                    mma16816(accO[mt][ntp*2+q2], ph[mt], v_l[q2]);
            #pragma unroll
            for (int mt = 0; mt < 2; mt++)
                #pragma unroll
                for (int q2 = 0; q2 < 2; q2++)
                    mma16816(accO[mt][ntp*2+q2], pl[mt], v_h[q2]);
        }
    }
    __syncthreads();   // last tile's ldmatrix done before smem reuse below

    // ---- cross-warp_n reduction (staged, reuses smem) ----
    float* sO   = (float*)smem;                 // [64][66]
    float* lred = (float*)(smem + 64*66*4);     // [64]
    #pragma unroll 1
    for (int stage = 0; stage < 4; stage++) {
        if (warp_n == stage) {
            #pragma unroll
            for (int mt = 0; mt < 2; mt++) {
                #pragma unroll
                for (int half = 0; half < 2; half++) {
                    int r = warp_m*32 + mt*16 + (lane >> 2) + half*8;
                    #pragma unroll
                    for (int nt = 0; nt < 8; nt++) {
                        int cc = nt*8 + (lane & 3)*2;
                        float v0 = accO[mt][nt][half*2 + 0];
                        float v1 = accO[mt][nt][half*2 + 1];
                        if (stage == 0) { sO[r*66+cc] = v0; sO[r*66+cc+1] = v1; }
                        else            { sO[r*66+cc] += v0; sO[r*66+cc+1] += v1; }
                    }
                    if ((lane & 3) == 0) {
                        if (stage == 0) lred[r] = l_acc[mt*2 + half];
                        else            lred[r] += l_acc[mt*2 + half];
                    }
                }
            }
        }
        __syncthreads();
    }

    // ---- normalize + write bf16 hi/lo token-major ----
    int b = bh >> 4, h = bh & 15;
    for (int p = tid; p < 4096; p += 256) {
        int t = p >> 6, d = p & 63;
        float v = sO[t*66 + d] / lred[t];
        __nv_bfloat16 hv = __float2bfloat16(v);
        size_t o = ((size_t)(b*SEQ + ib*64 + t))*DMODEL + h*64 + d;
        oh[o] = hv;
        ol[o] = __float2bfloat16(v - __bfloat162float(hv));
    }
}

// ============================================================
extern "C" void kernel_launch(void* const* d_in, const int* in_sizes, int n_in,
                              void* d_out, int out_size)
{
    (void)in_sizes; (void)n_in; (void)out_size;
    const float* x    = (const float*)d_in[0];
    const float* Wq   = (const float*)d_in[1];
    const float* Wk   = (const float*)d_in[2];
    const float* Wv   = (const float*)d_in[3];
    const float* Wo   = (const float*)d_in[4];
    const float* Wqm  = (const float*)d_in[5];
    const float* Wkm  = (const float*)d_in[6];
    const float* Wm   = (const float*)d_in[7];
    const float* temp = (const float*)d_in[8];

    float *q, *k, *ct, *st, *po;
    __nv_bfloat16 *xh, *xl, *wth, *wtl, *vh, *vl, *uh, *wwh, *wwl, *a2h, *a2l;
    cudaGetSymbolAddress((void**)&q,   g_q);
    cudaGetSymbolAddress((void**)&k,   g_k);
    cudaGetSymbolAddress((void**)&ct,  g_cos);
    cudaGetSymbolAddress((void**)&st,  g_sin);
    cudaGetSymbolAddress((void**)&po,  g_po);
    cudaGetSymbolAddress((void**)&xh,  g_xh);
    cudaGetSymbolAddress((void**)&xl,  g_xl);
    cudaGetSymbolAddress((void**)&wth, g_wth);
    cudaGetSymbolAddress((void**)&wtl, g_wtl);
    cudaGetSymbolAddress((void**)&vh,  g_vh);
    cudaGetSymbolAddress((void**)&vl,  g_vl);
    cudaGetSymbolAddress((void**)&uh,  g_uh);
    cudaGetSymbolAddress((void**)&wwh, g_wh);
    cudaGetSymbolAddress((void**)&wwl, g_wl);
    cudaGetSymbolAddress((void**)&a2h, g_a2h);
    cudaGetSymbolAddress((void**)&a2l, g_a2l);

    cudaFuncSetAttribute(mma_gemm<0>, cudaFuncAttributeMaxDynamicSharedMemorySize, GEMM_SMEM);
    cudaFuncSetAttribute(mma_gemm<1>, cudaFuncAttributeMaxDynamicSharedMemorySize, GEMM_SMEM);
    cudaFuncSetAttribute(flash_mma,  cudaFuncAttributeMaxDynamicSharedMemorySize, FLASH_SMEM);

    rope_table_kernel<<<(SEQ*32)/256, 256>>>(ct, st);
    wconv_kernel<<<dim3(32, 32, 4), dim3(32, 8)>>>(Wq, Wk, Wv, Wo, wth, wtl);
    xconv_kernel<<<(NTOK*DMODEL)/256, 256>>>(x, xh, xl);

    // fused QKV, role-interleaved (lid%3: v,q,k) for per-SM load balance
    size_t WSZ = (size_t)DMODEL*DMODEL;
    mma_gemm<1><<<dim3(DMODEL/128, NTOK/128, 3), 256, GEMM_SMEM>>>(
        xh, xl, wth, wtl, q, k, vh, vl);

    feature_kernel<<<NBHT/64, 64>>>(q, k, ct, st, Wqm, Wkm, Wm, uh, wwh, wwl);

    flash_mma<<<dim3(SEQ/64, BATCH*NHEADS), 256, FLASH_SMEM>>>(
        uh, wwh, wwl, vh, vl, a2h, a2l, temp);

    // final GEMM: K-split x2 into partials, then sum
    mma_gemm<0><<<dim3(DMODEL/128, NTOK/128, 2), 256, GEMM_SMEM>>>(
        a2h, a2l, wth + 3*WSZ, wtl + 3*WSZ, po, nullptr, nullptr, nullptr);
    sum_kernel<<<(NTOK*DMODEL)/256, 256>>>(po, (float*)d_out);
}

// round 17
// speedup vs baseline: 1.0656x; 1.0656x over previous
#include <cuda_runtime.h>
#include <cuda_bf16.h>
#include <math.h>
#include <stdint.h>

// Problem constants
#define BATCH   2
#define SEQ     1024
#define DMODEL  1024
#define NHEADS  16
#define DHEAD   64
#define NTOK    (BATCH*SEQ)          // 2048
#define NBHT    (BATCH*NHEADS*SEQ)   // 32768
#define FDIM    48                   // compressed feature dim (45 used, padded 48)
#define EPS_PSD 0.001f

// -------- device scratch (static, no allocations) --------
__device__ float g_q[NBHT*DHEAD];
__device__ float g_k[NBHT*DHEAD];
__device__ float g_cos[SEQ*32];
__device__ float g_sin[SEQ*32];
__device__ float g_po[2*NTOK*DMODEL];            // final gemm K-split partials

__device__ __nv_bfloat16 g_xh[NTOK*DMODEL];
__device__ __nv_bfloat16 g_xl[NTOK*DMODEL];
__device__ __nv_bfloat16 g_wth[4*DMODEL*DMODEL]; // Wq,Wk,Wv,Wo transposed [n][k]
__device__ __nv_bfloat16 g_wtl[4*DMODEL*DMODEL];

__device__ __nv_bfloat16 g_vh[NBHT*DHEAD];       // V bf16 hi/lo [bh][t][d]
__device__ __nv_bfloat16 g_vl[NBHT*DHEAD];

__device__ __nv_bfloat16 g_uh[NBHT*FDIM];        // u rows bf16 hi [n][48]
__device__ __nv_bfloat16 g_wh[NBHT*FDIM];        // w rows bf16 hi/lo [n][48]
__device__ __nv_bfloat16 g_wl[NBHT*FDIM];

__device__ __nv_bfloat16 g_a2h[NTOK*DMODEL];     // attention out, token-major
__device__ __nv_bfloat16 g_a2l[NTOK*DMODEL];

// ============================================================
// PTX helpers
// ============================================================
__device__ __forceinline__ uint32_t smem_u32(const void* p) {
    uint32_t a;
    asm("{ .reg .u64 t; cvta.to.shared.u64 t, %1; cvt.u32.u64 %0, t; }" : "=r"(a) : "l"(p));
    return a;
}
__device__ __forceinline__ void ldmatrix_x4(uint32_t* r, uint32_t addr) {
    asm volatile("ldmatrix.sync.aligned.m8n8.x4.shared.b16 {%0,%1,%2,%3}, [%4];"
        : "=r"(r[0]), "=r"(r[1]), "=r"(r[2]), "=r"(r[3]) : "r"(addr));
}
__device__ __forceinline__ void ldmatrix_x2(uint32_t* r, uint32_t addr) {
    asm volatile("ldmatrix.sync.aligned.m8n8.x2.shared.b16 {%0,%1}, [%2];"
        : "=r"(r[0]), "=r"(r[1]) : "r"(addr));
}
__device__ __forceinline__ void ldmatrix_x2_trans(uint32_t* r, uint32_t addr) {
    asm volatile("ldmatrix.sync.aligned.m8n8.x2.trans.shared.b16 {%0,%1}, [%2];"
        : "=r"(r[0]), "=r"(r[1]) : "r"(addr));
}
__device__ __forceinline__ void mma16816(float* c, const uint32_t* a, const uint32_t* b) {
    asm volatile("mma.sync.aligned.m16n8k16.row.col.f32.bf16.bf16.f32 "
        "{%0,%1,%2,%3}, {%4,%5,%6,%7}, {%8,%9}, {%0,%1,%2,%3};"
        : "+f"(c[0]), "+f"(c[1]), "+f"(c[2]), "+f"(c[3])
        : "r"(a[0]), "r"(a[1]), "r"(a[2]), "r"(a[3]), "r"(b[0]), "r"(b[1]));
}
#define CP_ASYNC16(saddr, gptr) \
    asm volatile("cp.async.cg.shared.global [%0], [%1], 16;" \
        :: "r"(saddr), "l"(gptr) : "memory")
#define CP_COMMIT() asm volatile("cp.async.commit_group;" ::: "memory")
#define CP_WAIT(N)  asm volatile("cp.async.wait_group %0;" :: "n"(N) : "memory")

__device__ __forceinline__ void split2(float v0, float v1, uint32_t& h, uint32_t& l) {
    __nv_bfloat16 h0 = __float2bfloat16(v0), h1 = __float2bfloat16(v1);
    __nv_bfloat162 hp; hp.x = h0; hp.y = h1;
    h = *(uint32_t*)&hp;
    __nv_bfloat16 l0 = __float2bfloat16(v0 - __bfloat162float(h0));
    __nv_bfloat16 l1 = __float2bfloat16(v1 - __bfloat162float(h1));
    __nv_bfloat162 lp; lp.x = l0; lp.y = l1;
    l = *(uint32_t*)&lp;
}

// ============================================================
// Conversion + table kernels
// ============================================================
__global__ void xconv_kernel(const float* __restrict__ x,
                             __nv_bfloat16* __restrict__ xh,
                             __nv_bfloat16* __restrict__ xl)
{
    int i = blockIdx.x * blockDim.x + threadIdx.x;
    if (i >= NTOK*DMODEL) return;
    float v = x[i];
    __nv_bfloat16 h = __float2bfloat16(v);
    xh[i] = h;
    xl[i] = __float2bfloat16(v - __bfloat162float(h));
}

__global__ void wconv_kernel(const float* __restrict__ W0, const float* __restrict__ W1,
                             const float* __restrict__ W2, const float* __restrict__ W3,
                             __nv_bfloat16* __restrict__ th, __nv_bfloat16* __restrict__ tl)
{
    __shared__ float s[32][33];
    const float* W = (blockIdx.z == 0) ? W0 : (blockIdx.z == 1) ? W1
                   : (blockIdx.z == 2) ? W2 : W3;
    size_t zoff = (size_t)blockIdx.z * DMODEL * DMODEL;
    bool need_lo = (blockIdx.z >= 2);   // Wq/Wk used at bf16x1 (hi only)
    int n0 = blockIdx.x * 32, k0 = blockIdx.y * 32;
    int tx = threadIdx.x, ty = threadIdx.y;   // 32 x 8
    #pragma unroll
    for (int j = 0; j < 4; j++)
        s[ty + j*8][tx] = W[(size_t)(k0 + ty + j*8)*DMODEL + n0 + tx];
    __syncthreads();
    #pragma unroll
    for (int j = 0; j < 4; j++) {
        float v = s[tx][ty + j*8];
        __nv_bfloat16 h = __float2bfloat16(v);
        size_t o = zoff + (size_t)(n0 + ty + j*8)*DMODEL + k0 + tx;
        th[o] = h;
        if (need_lo) tl[o] = __float2bfloat16(v - __bfloat162float(h));
    }
}

__global__ void rope_table_kernel(float* __restrict__ ct, float* __restrict__ st)
{
    int idx = blockIdx.x * blockDim.x + threadIdx.x;
    if (idx >= SEQ*32) return;
    int i = idx & 31, t = idx >> 5;
    float inv = (float)(1.0 / pow(10000.0, (double)i / 32.0));
    float ang = (float)t * inv;
    float s, c;
    sincosf(ang, &s, &c);
    ct[idx] = c;
    st[idx] = s;
}

// sum the two final-gemm K-split partials into d_out
__global__ void sum_kernel(const float* __restrict__ po, float* __restrict__ out)
{
    int i = blockIdx.x * blockDim.x + threadIdx.x;
    if (i >= NTOK*DMODEL) return;
    out[i] = po[i] + po[NTOK*DMODEL + i];
}

// ============================================================
// mma.sync bf16 split GEMM, 128x128 CTA tile, 8 warps (2m x 4n),
// warp = 64x32 via 4x4 m16n8k16; mt-half inner loop; 2-stage
// cp.async, single sync per chunk; 2 CTAs/SM.
// MODE 0: half-K (z = k-half), f32 partial out [z][M][N], bf16x3.
// MODE 1: full-K fused QKV, natural z order (light q/k first, V last —
//   light CTAs drain fast, V CTAs backfill ~1/SM; measured-best layout).
//   z=0(q),1(k): bf16x1 (hi*hi only), f32 scatter. z=2(v): bf16x3,
//   bf16 hi/lo scatter.
// ============================================================
#define KC 32
#define ROW_STRIDE 40
#define MAT_BYTES (128*ROW_STRIDE*2)       // 10240
#define STAGE_BYTES (4*MAT_BYTES)          // 40960 (Ah, Al, Bh, Bl)
#define GEMM_SMEM (2*STAGE_BYTES)          // 81920

template<int MODE>
__global__ __launch_bounds__(256, 2)
void mma_gemm(const __nv_bfloat16* __restrict__ Ah, const __nv_bfloat16* __restrict__ Al,
              const __nv_bfloat16* __restrict__ Bh0, const __nv_bfloat16* __restrict__ Bl0,
              float* __restrict__ C0, float* __restrict__ C1,
              __nv_bfloat16* __restrict__ Cvh, __nv_bfloat16* __restrict__ Cvl)
{
    extern __shared__ char smem[];
    uint32_t sbase = smem_u32(smem);
    int tid = threadIdx.x, wid = tid >> 5, lane = tid & 31;
    int n0 = blockIdx.x * 128, m0 = blockIdx.y * 128;
    int z = blockIdx.z;
    const int KTOT = (MODE == 0) ? 512 : 1024;
    int koff = (MODE == 0) ? z * 512 : 0;
    const bool x3 = (MODE == 0) || (z == 2);   // uniform per CTA; else bf16x1

    const __nv_bfloat16* Bh = Bh0 + ((MODE == 1) ? (size_t)z * DMODEL * DMODEL : 0);
    const __nv_bfloat16* Bl = Bl0 + ((MODE == 1) ? (size_t)z * DMODEL * DMODEL : 0);

    int mat = tid >> 6;        // 0=Ah 1=Al 2=Bh 3=Bl
    int tp  = tid & 63;
    // x1 mode: Al/Bl unused; mats 0,1 split Ah rows; mats 2,3 split Bh rows.
    int srcmat = mat;
    int itlo = 0, ithi = 8;
    if (!x3) {
        if (mat == 0)      { ithi = 4; }
        else if (mat == 1) { srcmat = 0; itlo = 4; }
        else if (mat == 2) { ithi = 4; }
        else               { srcmat = 2; itlo = 4; }
    }
    const __nv_bfloat16* gsrc =
        (srcmat == 0) ? Ah + (size_t)m0*DMODEL + koff :
        (srcmat == 1) ? Al + (size_t)m0*DMODEL + koff :
        (srcmat == 2) ? Bh + (size_t)n0*DMODEL + koff :
                        Bl + (size_t)n0*DMODEL + koff;
    uint32_t moff = (uint32_t)srcmat * MAT_BYTES;

    int warp_m = wid & 1, warp_n = wid >> 1;

    float acc[4][4][4];
    #pragma unroll
    for (int a = 0; a < 4; a++)
        #pragma unroll
        for (int b = 0; b < 4; b++)
            #pragma unroll
            for (int c = 0; c < 4; c++) acc[a][b][c] = 0.f;

    #define GEMM_ISSUE(chunk, slot) do { \
        const __nv_bfloat16* g = gsrc + (chunk)*KC; \
        uint32_t sdst = sbase + (slot)*STAGE_BYTES + moff; \
        for (int it = itlo; it < ithi; it++) { \
            int idx = tp + it*64; \
            int row = idx >> 2, c4 = idx & 3; \
            CP_ASYNC16(sdst + row*(ROW_STRIDE*2) + c4*16, \
                       g + (size_t)row*DMODEL + c4*8); \
        } \
        CP_COMMIT(); \
    } while (0)

    GEMM_ISSUE(0, 0);

    for (int c = 0; c < KTOT/KC; c++) {
        int slot = c & 1;
        CP_WAIT(0);
        __syncthreads();
        if (c + 1 < KTOT/KC) GEMM_ISSUE(c + 1, slot ^ 1);

        uint32_t b_off = sbase + slot*STAGE_BYTES;
        #pragma unroll
        for (int ks = 0; ks < 2; ks++) {
            int k0 = ks * 16;
            uint32_t b_h[4][2], b_l[4][2];
            #pragma unroll
            for (int ntp = 0; ntp < 2; ntp++) {
                int row = warp_n*32 + ntp*16 + (lane & 7) + ((lane >> 4) << 3);
                uint32_t col = k0 + (((lane >> 3) & 1) << 3);
                uint32_t off = b_off + 2*MAT_BYTES + (row*ROW_STRIDE + col)*2;
                uint32_t rh[4], rl[4];
                ldmatrix_x4(rh, off);
                b_h[ntp*2+0][0] = rh[0]; b_h[ntp*2+0][1] = rh[1];
                b_h[ntp*2+1][0] = rh[2]; b_h[ntp*2+1][1] = rh[3];
                if (x3) {
                    ldmatrix_x4(rl, off + MAT_BYTES);
                    b_l[ntp*2+0][0] = rl[0]; b_l[ntp*2+0][1] = rl[1];
                    b_l[ntp*2+1][0] = rl[2]; b_l[ntp*2+1][1] = rl[3];
                }
            }
            #pragma unroll
            for (int half = 0; half < 2; half++) {
                uint32_t a_h[2][4], a_l[2][4];
                #pragma unroll
                for (int m2 = 0; m2 < 2; m2++) {
                    int mt = half*2 + m2;
                    int row = warp_m*64 + mt*16 + (lane & 15);
                    uint32_t col = k0 + ((lane >> 4) << 3);
                    uint32_t off = b_off + (row*ROW_STRIDE + col)*2;
                    ldmatrix_x4(a_h[m2], off);
                    if (x3) ldmatrix_x4(a_l[m2], off + MAT_BYTES);
                }
                #pragma unroll
                for (int m2 = 0; m2 < 2; m2++)
                    #pragma unroll
                    for (int nt = 0; nt < 4; nt++)
                        mma16816(acc[half*2+m2][nt], a_h[m2], b_h[nt]);
                if (x3) {
                    #pragma unroll
                    for (int m2 = 0; m2 < 2; m2++)
                        #pragma unroll
                        for (int nt = 0; nt < 4; nt++)
                            mma16816(acc[half*2+m2][nt], a_h[m2], b_l[nt]);
                    #pragma unroll
                    for (int m2 = 0; m2 < 2; m2++)
                        #pragma unroll
                        for (int nt = 0; nt < 4; nt++)
                            mma16816(acc[half*2+m2][nt], a_l[m2], b_h[nt]);
                }
            }
        }
    }

    // epilogue
    int qrow = lane >> 2, qcol = (lane & 3) * 2;
    float* Cp = (MODE == 0) ? (C0 + (size_t)z * NTOK * DMODEL) : nullptr;
    #pragma unroll
    for (int mt = 0; mt < 4; mt++) {
        #pragma unroll
        for (int nt = 0; nt < 4; nt++) {
            int row0 = m0 + warp_m*64 + mt*16 + qrow;
            int col  = n0 + warp_n*32 + nt*8 + qcol;
            float2 v0 = make_float2(acc[mt][nt][0], acc[mt][nt][1]);
            float2 v1 = make_float2(acc[mt][nt][2], acc[mt][nt][3]);
            if (MODE == 0) {
                *(float2*)&Cp[(size_t)row0*DMODEL + col] = v0;
                *(float2*)&Cp[(size_t)(row0 + 8)*DMODEL + col] = v1;
            } else if (z < 2) {
                float* C = z ? C1 : C0;
                int h = col >> 6, d = col & 63;
                int b0 = row0 >> 10, t0 = row0 & 1023;
                *(float2*)&C[((size_t)((b0*NHEADS + h)*SEQ + t0))*DHEAD + d] = v0;
                int r1 = row0 + 8;
                int b1 = r1 >> 10, t1 = r1 & 1023;
                *(float2*)&C[((size_t)((b1*NHEADS + h)*SEQ + t1))*DHEAD + d] = v1;
            } else {
                int h = col >> 6, d = col & 63;
                #pragma unroll
                for (int rr = 0; rr < 2; rr++) {
                    int row = row0 + rr*8;
                    float2 v = rr ? v1 : v0;
                    int b = row >> 10, t = row & 1023;
                    size_t o = ((size_t)((b*NHEADS + h)*SEQ + t))*DHEAD + d;
                    __nv_bfloat16 h0 = __float2bfloat16(v.x), h1 = __float2bfloat16(v.y);
                    __nv_bfloat162 hp; hp.x = h0; hp.y = h1;
                    *(__nv_bfloat162*)&Cvh[o] = hp;
                    __nv_bfloat162 lp;
                    lp.x = __float2bfloat16(v.x - __bfloat162float(h0));
                    lp.y = __float2bfloat16(v.y - __bfloat162float(h1));
                    *(__nv_bfloat162*)&Cvl[o] = lp;
                }
            }
        }
    }
}

// ============================================================
// Feature kernel, fused RoPE -> compressed 48-dim features.
// u rows: bf16 hi only. w rows: bf16 hi/lo.
// Feature layout (45 used):
//   [0..7]   u=2*Gq[d],        w=km[d]
//   [8..15]  u=-G[d][d],       w=km[d]^2
//   [16..43] u=-2*G[d][f] d<f, w=km[d]*km[f]
//   [44]     u=-qGq,           w=1
//   [45..47] zero padding
// ============================================================
__global__ void feature_kernel(const float* __restrict__ q, const float* __restrict__ k,
                               const float* __restrict__ ct, const float* __restrict__ st,
                               const float* __restrict__ Wqm, const float* __restrict__ Wkm,
                               const float* __restrict__ Wm,
                               __nv_bfloat16* __restrict__ uhg,
                               __nv_bfloat16* __restrict__ whg, __nv_bfloat16* __restrict__ wlg)
{
    __shared__ float sWqm[512], sWkm[512], sWm[512];
    __shared__ float sOut[64][51];

    int tid = threadIdx.x;           // 64 threads
    int n0 = blockIdx.x * 64;
    int n  = n0 + tid;
    int t  = n & 1023;

    for (int p = tid; p < 512; p += 64) {
        sWqm[p] = Wqm[p]; sWkm[p] = Wkm[p]; sWm[p] = Wm[p];
    }
    __syncthreads();

    const float4* qr = (const float4*)(q + (size_t)n*64);
    const float4* kr = (const float4*)(k + (size_t)n*64);
    const float4* cp4 = (const float4*)(ct + (size_t)t*32);
    const float4* sp4 = (const float4*)(st + (size_t)t*32);

    float qm[8], km[8];
    #pragma unroll
    for (int m = 0; m < 8; m++) { qm[m] = 0.f; km[m] = 0.f; }
    #pragma unroll
    for (int d4 = 0; d4 < 8; d4++) {
        float4 q1 = qr[d4], q2 = qr[d4+8];
        float4 k1 = kr[d4], k2 = kr[d4+8];
        float4 cv = cp4[d4], sv = sp4[d4];
        const float* q1f = (const float*)&q1;
        const float* q2f = (const float*)&q2;
        const float* k1f = (const float*)&k1;
        const float* k2f = (const float*)&k2;
        const float* cf  = (const float*)&cv;
        const float* sf  = (const float*)&sv;
        #pragma unroll
        for (int j = 0; j < 4; j++) {
            int i = d4*4 + j;
            float c = cf[j], s = sf[j];
            float qa = q1f[j]*c - q2f[j]*s;
            float qb = q1f[j]*s + q2f[j]*c;
            float ka = k1f[j]*c - k2f[j]*s;
            float kb = k1f[j]*s + k2f[j]*c;
            #pragma unroll
            for (int m = 0; m < 8; m++) {
                qm[m] = fmaf(qa, sWqm[i*8+m], fmaf(qb, sWqm[(i+32)*8+m], qm[m]));
                km[m] = fmaf(ka, sWkm[i*8+m], fmaf(kb, sWkm[(i+32)*8+m], km[m]));
            }
        }
    }
    #pragma unroll
    for (int m = 0; m < 8; m++) {
        qm[m] = 1.0f / (1.0f + expf(-qm[m]));
        km[m] = 1.0f / (1.0f + expf(-km[m]));
    }

    float A[64];
    #pragma unroll
    for (int nn = 0; nn < 64; nn++) {
        float s = 0.f;
        #pragma unroll
        for (int m = 0; m < 8; m++) s = fmaf(qm[m], sWm[m*64+nn], s);
        A[nn] = s;
    }

    // G symmetric: compute diag + upper triangle only
    float Gq[8];
    #pragma unroll
    for (int d = 0; d < 8; d++) Gq[d] = 0.f;
    {
        int pc = 16;
        #pragma unroll
        for (int d = 0; d < 8; d++) {
            #pragma unroll
            for (int f = d; f < 8; f++) {
                float g = 0.f;
                #pragma unroll
                for (int e = 0; e < 8; e++) g = fmaf(A[d*8+e], A[f*8+e], g);
                if (f == d) {
                    g += EPS_PSD;
                    sOut[tid][8 + d] = -g;
                    Gq[d] = fmaf(g, qm[d], Gq[d]);
                } else {
                    sOut[tid][pc++] = -2.0f * g;
                    Gq[d] = fmaf(g, qm[f], Gq[d]);
                    Gq[f] = fmaf(g, qm[d], Gq[f]);
                }
            }
        }
    }
    float qGq = 0.f;
    #pragma unroll
    for (int d = 0; d < 8; d++) {
        qGq = fmaf(Gq[d], qm[d], qGq);
        sOut[tid][d] = 2.0f * Gq[d];
    }
    sOut[tid][44] = -qGq;
    sOut[tid][45] = 0.f; sOut[tid][46] = 0.f; sOut[tid][47] = 0.f;
    __syncthreads();

    // u: hi only
    for (int p = tid; p < 64*FDIM; p += 64) {
        int r = p / FDIM, c = p % FDIM;
        uhg[(size_t)(n0 + r)*FDIM + c] = __float2bfloat16(sOut[r][c]);
    }
    __syncthreads();

    // w features
    {
        #pragma unroll
        for (int d = 0; d < 8; d++) sOut[tid][d] = km[d];
        #pragma unroll
        for (int d = 0; d < 8; d++) sOut[tid][8 + d] = km[d]*km[d];
        int pc = 16;
        #pragma unroll
        for (int d = 0; d < 8; d++)
            #pragma unroll
            for (int f = d+1; f < 8; f++)
                sOut[tid][pc++] = km[d]*km[f];
        sOut[tid][44] = 1.0f;
        sOut[tid][45] = 0.f; sOut[tid][46] = 0.f; sOut[tid][47] = 0.f;
    }
    __syncthreads();

    for (int p = tid; p < 64*FDIM; p += 64) {
        int r = p / FDIM, c = p % FDIM;
        float v = sOut[r][c];
        __nv_bfloat16 h = __float2bfloat16(v);
        size_t o = (size_t)(n0 + r)*FDIM + c;
        whg[o] = h;
        wlg[o] = __float2bfloat16(v - __bfloat162float(h));
    }
}

// ============================================================
// Tensor-core flash on 48-dim features:
// S = U.W^T with U hi-only (bf16x2: uh*wh + uh*wl), 3 k-steps;
// P = exp(min(S,0)/temp) (S<=0, no max tracking); O = P.V (bf16x3);
// split-k over warp_n. 64x64 tiles, 8 warps; 2-stage cp.async; 2 CTAs/SM.
// ============================================================
#define FL_USTR 56
#define FL_VSTR 72
#define FL_UMAT (64*FL_USTR*2)              // 7168
#define FL_OFF_W  FL_UMAT                   // 7168
#define FL_WBUF   (2*FL_UMAT)               // 14336 (h + l)
#define FL_OFF_V  (FL_OFF_W + 2*FL_WBUF)    // 35840
#define FL_VBUF   (2*64*FL_VSTR*2)          // 18432
#define FLASH_SMEM (FL_OFF_V + 2*FL_VBUF)   // 72704

__global__ __launch_bounds__(256, 2)
void flash_mma(const __nv_bfloat16* __restrict__ uh,
               const __nv_bfloat16* __restrict__ wh, const __nv_bfloat16* __restrict__ wl,
               const __nv_bfloat16* __restrict__ vh, const __nv_bfloat16* __restrict__ vl,
               __nv_bfloat16* __restrict__ oh, __nv_bfloat16* __restrict__ ol,
               const float* __restrict__ temperature)
{
    extern __shared__ char smem[];
    uint32_t sb = smem_u32(smem);
    int tid = threadIdx.x, wid = tid >> 5, lane = tid & 31;
    int warp_m = wid & 1, warp_n = wid >> 1;
    int bh = blockIdx.y;
    int ib = (int)(gridDim.x - 1 - blockIdx.x);
    float inv_temp = 1.f / fmaxf(temperature[0], 0.1f);

    // U tile load (hi only: 64 rows x 96B, stride 112B)
    {
        const char* gh = (const char*)(uh + (size_t)(bh*SEQ + ib*64)*FDIM);
        for (int p = tid; p < 384; p += 256) {
            int r = p / 6, c = p % 6;
            CP_ASYNC16(sb + r*(FL_USTR*2) + c*16, gh + r*96 + c*16);
        }
    }
    #define ISSUE_WV(jb, buf) do { \
        const char* gwh = (const char*)(wh + (size_t)(bh*SEQ + (jb)*64)*FDIM); \
        const char* gwl = (const char*)(wl + (size_t)(bh*SEQ + (jb)*64)*FDIM); \
        uint32_t wdst = sb + FL_OFF_W + (buf)*FL_WBUF; \
        for (int p = tid; p < 384; p += 256) { \
            int r = p / 6, c = p % 6; \
            CP_ASYNC16(wdst + r*(FL_USTR*2) + c*16, gwh + r*96 + c*16); \
            CP_ASYNC16(wdst + FL_UMAT + r*(FL_USTR*2) + c*16, gwl + r*96 + c*16); \
        } \
        const char* gvh = (const char*)(vh + (size_t)(bh*SEQ + (jb)*64)*DHEAD); \
        const char* gvl = (const char*)(vl + (size_t)(bh*SEQ + (jb)*64)*DHEAD); \
        uint32_t vdst = sb + FL_OFF_V + (buf)*FL_VBUF; \
        for (int p = tid; p < 512; p += 256) { \
            int r = p / 8, c = p % 8; \
            CP_ASYNC16(vdst + r*144 + c*16, gvh + r*128 + c*16); \
            CP_ASYNC16(vdst + 9216 + r*144 + c*16, gvl + r*128 + c*16); \
        } \
    } while (0)

    ISSUE_WV(0, 0);
    CP_COMMIT();

    float accO[2][8][4];
    float l_acc[4];
    #pragma unroll
    for (int i = 0; i < 4; i++) l_acc[i] = 0.f;
    #pragma unroll
    for (int mt = 0; mt < 2; mt++)
        #pragma unroll
        for (int nt = 0; nt < 8; nt++)
            #pragma unroll
            for (int r = 0; r < 4; r++) accO[mt][nt][r] = 0.f;

    for (int jb = 0; jb <= ib; jb++) {
        int buf = jb & 1;
        CP_WAIT(0);
        __syncthreads();
        if (jb < ib) { ISSUE_WV(jb+1, buf^1); CP_COMMIT(); }

        uint32_t sw_h = sb + FL_OFF_W + buf*FL_WBUF;
        uint32_t sw_l = sw_h + FL_UMAT;
        uint32_t sv_h = sb + FL_OFF_V + buf*FL_VBUF;
        uint32_t sv_l = sv_h + 9216;

        // ---- S = U . W^T  (bf16x2, 3 k-steps over 48 features) ----
        float sc[2][2][4];
        #pragma unroll
        for (int mt = 0; mt < 2; mt++)
            #pragma unroll
            for (int nt = 0; nt < 2; nt++)
                #pragma unroll
                for (int r = 0; r < 4; r++) sc[mt][nt][r] = 0.f;

        #pragma unroll
        for (int k5 = 0; k5 < 3; k5++) {
            int k0 = k5*16;
            uint32_t a_h[2][4], b_h[2][2], b_l[2][2];
            #pragma unroll
            for (int mt = 0; mt < 2; mt++) {
                int row = warp_m*32 + mt*16 + (lane & 15);
                uint32_t off = (uint32_t)(row*FL_USTR + k0 + ((lane >> 4) << 3))*2;
                ldmatrix_x4(a_h[mt], sb + off);
            }
            #pragma unroll
            for (int nt = 0; nt < 2; nt++) {
                int row = warp_n*16 + nt*8 + (lane & 7);
                uint32_t off = (uint32_t)(row*FL_USTR + k0 + (((lane >> 3) & 1) << 3))*2;
                ldmatrix_x2(b_h[nt], sw_h + off);
                ldmatrix_x2(b_l[nt], sw_l + off);
            }
            #pragma unroll
            for (int mt = 0; mt < 2; mt++)
                #pragma unroll
                for (int nt = 0; nt < 2; nt++)
                    mma16816(sc[mt][nt], a_h[mt], b_h[nt]);
            #pragma unroll
            for (int mt = 0; mt < 2; mt++)
                #pragma unroll
                for (int nt = 0; nt < 2; nt++)
                    mma16816(sc[mt][nt], a_h[mt], b_l[nt]);
        }

        // ---- P = exp(min(S,0)/temp), causal mask, row-sum partials ----
        bool diag = (jb == ib);
        uint32_t ph[2][4], pl[2][4];
        #pragma unroll
        for (int mt = 0; mt < 2; mt++) {
            #pragma unroll
            for (int half = 0; half < 2; half++) {
                int t_g = ib*64 + warp_m*32 + mt*16 + (lane >> 2) + half*8;
                float pv[4];
                #pragma unroll
                for (int nt = 0; nt < 2; nt++) {
                    #pragma unroll
                    for (int cc = 0; cc < 2; cc++) {
                        int s_g = jb*64 + warp_n*16 + nt*8 + (lane & 3)*2 + cc;
                        float v = sc[mt][nt][half*2 + cc];
                        float p = __expf(fminf(v, 0.f) * inv_temp);
                        if (diag && s_g > t_g) p = 0.f;
                        pv[nt*2 + cc] = p;
                    }
                }
                float ls = pv[0] + pv[1] + pv[2] + pv[3];
                ls += __shfl_xor_sync(0xffffffffu, ls, 1);
                ls += __shfl_xor_sync(0xffffffffu, ls, 2);
                l_acc[mt*2 + half] += ls;
                split2(pv[0], pv[1], ph[mt][half], pl[mt][half]);
                split2(pv[2], pv[3], ph[mt][2 + half], pl[mt][2 + half]);
            }
        }

        // ---- O += P . V  (k-slice = warp_n's 16 s) ----
        #pragma unroll
        for (int ntp = 0; ntp < 4; ntp++) {
            uint32_t v_h[2][2], v_l[2][2];
            #pragma unroll
            for (int q2 = 0; q2 < 2; q2++) {
                int nt = ntp*2 + q2;
                uint32_t off = (uint32_t)((warp_n*16 + (lane & 15))*FL_VSTR + nt*8)*2;
                ldmatrix_x2_trans(v_h[q2], sv_h + off);
                ldmatrix_x2_trans(v_l[q2], sv_l + off);
            }
            #pragma unroll
            for (int mt = 0; mt < 2; mt++)
                #pragma unroll
                for (int q2 = 0; q2 < 2; q2++)
                    mma16816(accO[mt][ntp*2+q2], ph[mt], v_h[q2]);
            #pragma unroll
            for (int mt = 0; mt < 2; mt++)
                #pragma unroll
                for (int q2 = 0; q2 < 2; q2++)
                    mma16816(accO[mt][ntp*2+q2], ph[mt], v_l[q2]);
            #pragma unroll
            for (int mt = 0; mt < 2; mt++)
                #pragma unroll
                for (int q2 = 0; q2 < 2; q2++)
                    mma16816(accO[mt][ntp*2+q2], pl[mt], v_h[q2]);
        }
    }
    __syncthreads();   // last tile's ldmatrix done before smem reuse below

    // ---- cross-warp_n reduction (staged, reuses smem) ----
    float* sO   = (float*)smem;                 // [64][66]
    float* lred = (float*)(smem + 64*66*4);     // [64]
    #pragma unroll 1
    for (int stage = 0; stage < 4; stage++) {
        if (warp_n == stage) {
            #pragma unroll
            for (int mt = 0; mt < 2; mt++) {
                #pragma unroll
                for (int half = 0; half < 2; half++) {
                    int r = warp_m*32 + mt*16 + (lane >> 2) + half*8;
                    #pragma unroll
                    for (int nt = 0; nt < 8; nt++) {
                        int cc = nt*8 + (lane & 3)*2;
                        float v0 = accO[mt][nt][half*2 + 0];
                        float v1 = accO[mt][nt][half*2 + 1];
                        if (stage == 0) { sO[r*66+cc] = v0; sO[r*66+cc+1] = v1; }
                        else            { sO[r*66+cc] += v0; sO[r*66+cc+1] += v1; }
                    }
                    if ((lane & 3) == 0) {
                        if (stage == 0) lred[r] = l_acc[mt*2 + half];
                        else            lred[r] += l_acc[mt*2 + half];
                    }
                }
            }
        }
        __syncthreads();
    }

    // ---- normalize + write bf16 hi/lo token-major ----
    int b = bh >> 4, h = bh & 15;
    for (int p = tid; p < 4096; p += 256) {
        int t = p >> 6, d = p & 63;
        float v = sO[t*66 + d] / lred[t];
        __nv_bfloat16 hv = __float2bfloat16(v);
        size_t o = ((size_t)(b*SEQ + ib*64 + t))*DMODEL + h*64 + d;
        oh[o] = hv;
        ol[o] = __float2bfloat16(v - __bfloat162float(hv));
    }
}

// ============================================================
extern "C" void kernel_launch(void* const* d_in, const int* in_sizes, int n_in,
                              void* d_out, int out_size)
{
    (void)in_sizes; (void)n_in; (void)out_size;
    const float* x    = (const float*)d_in[0];
    const float* Wq   = (const float*)d_in[1];
    const float* Wk   = (const float*)d_in[2];
    const float* Wv   = (const float*)d_in[3];
    const float* Wo   = (const float*)d_in[4];
    const float* Wqm  = (const float*)d_in[5];
    const float* Wkm  = (const float*)d_in[6];
    const float* Wm   = (const float*)d_in[7];
    const float* temp = (const float*)d_in[8];

    float *q, *k, *ct, *st, *po;
    __nv_bfloat16 *xh, *xl, *wth, *wtl, *vh, *vl, *uh, *wwh, *wwl, *a2h, *a2l;
    cudaGetSymbolAddress((void**)&q,   g_q);
    cudaGetSymbolAddress((void**)&k,   g_k);
    cudaGetSymbolAddress((void**)&ct,  g_cos);
    cudaGetSymbolAddress((void**)&st,  g_sin);
    cudaGetSymbolAddress((void**)&po,  g_po);
    cudaGetSymbolAddress((void**)&xh,  g_xh);
    cudaGetSymbolAddress((void**)&xl,  g_xl);
    cudaGetSymbolAddress((void**)&wth, g_wth);
    cudaGetSymbolAddress((void**)&wtl, g_wtl);
    cudaGetSymbolAddress((void**)&vh,  g_vh);
    cudaGetSymbolAddress((void**)&vl,  g_vl);
    cudaGetSymbolAddress((void**)&uh,  g_uh);
    cudaGetSymbolAddress((void**)&wwh, g_wh);
    cudaGetSymbolAddress((void**)&wwl, g_wl);
    cudaGetSymbolAddress((void**)&a2h, g_a2h);
    cudaGetSymbolAddress((void**)&a2l, g_a2l);

    cudaFuncSetAttribute(mma_gemm<0>, cudaFuncAttributeMaxDynamicSharedMemorySize, GEMM_SMEM);
    cudaFuncSetAttribute(mma_gemm<1>, cudaFuncAttributeMaxDynamicSharedMemorySize, GEMM_SMEM);
    cudaFuncSetAttribute(flash_mma,  cudaFuncAttributeMaxDynamicSharedMemorySize, FLASH_SMEM);

    rope_table_kernel<<<(SEQ*32)/256, 256>>>(ct, st);
    wconv_kernel<<<dim3(32, 32, 4), dim3(32, 8)>>>(Wq, Wk, Wv, Wo, wth, wtl);
    xconv_kernel<<<(NTOK*DMODEL)/256, 256>>>(x, xh, xl);

    // fused QKV, natural z order (z=0 q, z=1 k: bf16x1; z=2 v: bf16x3)
    size_t WSZ = (size_t)DMODEL*DMODEL;
    mma_gemm<1><<<dim3(DMODEL/128, NTOK/128, 3), 256, GEMM_SMEM>>>(
        xh, xl, wth, wtl, q, k, vh, vl);

    feature_kernel<<<NBHT/64, 64>>>(q, k, ct, st, Wqm, Wkm, Wm, uh, wwh, wwl);

    flash_mma<<<dim3(SEQ/64, BATCH*NHEADS), 256, FLASH_SMEM>>>(
        uh, wwh, wwl, vh, vl, a2h, a2l, temp);

    // final GEMM: K-split x2 into partials, then sum
    mma_gemm<0><<<dim3(DMODEL/128, NTOK/128, 2), 256, GEMM_SMEM>>>(
        a2h, a2l, wth + 3*WSZ, wtl + 3*WSZ, po, nullptr, nullptr, nullptr);
    sum_kernel<<<(NTOK*DMODEL)/256, 256>>>(po, (float*)d_out);
}